// round 3
// baseline (speedup 1.0000x reference)
#include <cuda_runtime.h>

// Shapes (fixed by the problem):
//   state: [64, 128, 16]
//   block1: cols=16   -> x1 [64, 128ch, 124]
//   block2: cols=128  -> x2 [64, 1024ch, 120]
//   block3: cols=1024 -> x3 [64, 8192ch, 116] (FUSED with dense, never stored)
//   dense:  feat = t*8192 + ch3, W [950272, 2], out = tanh(x@W + bd), [64, 2]

#define Bz   64
#define Lin  128
#define Cin  16
#define KW   5
#define NF   8
#define L1   124
#define CH1  128
#define L2   120
#define CH2  1024
#define L3   116
#define CH3  8192

// Scratch (allocation-free rule: __device__ globals)
__device__ float g_x1[Bz * CH1 * L1];            // 4.06 MB
__device__ float g_x2[Bz * CH2 * L2];            // 31.5 MB
__device__ float g_partial[128 * 32];            // [b*2+a] at stride 32 floats (128B) -> distinct L2 lines for atomics

// ---------------------------------------------------------------------------
// Block 1: one CTA per (c, b). 16x64 grid, 128 threads.
// ---------------------------------------------------------------------------
__global__ void k_block1(const float* __restrict__ state,
                         const float* __restrict__ k1,
                         const float* __restrict__ b1) {
    const int c = blockIdx.x, b = blockIdx.y, tid = threadIdx.x;

    // Zero the atomic partial buffer (stream order guarantees this precedes kernel 3)
    if (blockIdx.x == 0 && blockIdx.y == 0) {
        for (int j = tid; j < 128 * 32; j += 128) g_partial[j] = 0.f;
    }

    __shared__ float ssh[Lin];
    __shared__ float wsh[KW * NF];
    __shared__ float bsh[NF];

    ssh[tid] = state[(b * Lin + tid) * Cin + c];                // x[b,c,l] = state[b,l,c]
    if (tid < KW * NF) wsh[tid] = k1[(tid >> 3) * CH1 + c * NF + (tid & 7)];
    if (tid < NF)      bsh[tid] = b1[c * NF + tid];
    __syncthreads();

    for (int i = tid; i < NF * L1; i += 128) {
        int f = i / L1, t = i - f * L1;
        float y = bsh[f];
        #pragma unroll
        for (int k = 0; k < KW; k++) y = fmaf(ssh[t + k], wsh[k * NF + f], y);
        g_x1[(b * CH1 + c * NF + f) * L1 + t] = fmaxf(y, 0.f);
    }
}

// ---------------------------------------------------------------------------
// Block 2: one CTA per (g, b). 128x64 grid, 128 threads.
// ---------------------------------------------------------------------------
__global__ void k_block2(const float* __restrict__ k2,
                         const float* __restrict__ b2) {
    const int g = blockIdx.x, b = blockIdx.y, tid = threadIdx.x;

    __shared__ float xsh[L1];
    __shared__ float wsh[KW * NF];
    __shared__ float bsh[NF];

    if (tid < L1)      xsh[tid] = g_x1[(b * CH1 + g) * L1 + tid];
    if (tid < KW * NF) wsh[tid] = k2[(tid >> 3) * CH2 + g * NF + (tid & 7)];
    if (tid < NF)      bsh[tid] = b2[g * NF + tid];
    __syncthreads();

    for (int i = tid; i < NF * L2; i += 128) {
        int f = i / L2, t = i - f * L2;
        float y = bsh[f];
        #pragma unroll
        for (int k = 0; k < KW; k++) y = fmaf(xsh[t + k], wsh[k * NF + f], y);
        g_x2[(b * CH2 + g * NF + f) * L2 + t] = fmaxf(y, 0.f);
    }
}

// ---------------------------------------------------------------------------
// Block 3 + dense, fused. One CTA per channel-group g in [0,1024).
// The W slice and x2 slice owned by a group are disjoint across groups, so
// every byte is read exactly once from DRAM. 256 threads = 4 threads per batch,
// each thread owns a contiguous 29-position t-range with a 5-wide sliding window.
// ---------------------------------------------------------------------------
__global__ void __launch_bounds__(256) k_block3_dense(
        const float* __restrict__ k3,
        const float* __restrict__ b3,
        const float* __restrict__ W) {
    const int g = blockIdx.x, tid = threadIdx.x;

    __shared__ float  xall[Bz * L2];        // 30720 B: x2[b, g, t] for all b
    __shared__ float2 Wsh[L3 * NF];         // 7424 B:  W[t*8192 + g*8 + f, {0,1}]
    __shared__ float  w3sh[KW * NF];
    __shared__ float  b3sh[NF];

    const float2* __restrict__ W2 = (const float2*)W;

    for (int i = tid; i < Bz * L2; i += 256) {
        int bb = i / L2, t = i - bb * L2;
        xall[i] = g_x2[(bb * CH2 + g) * L2 + t];
    }
    for (int i = tid; i < L3 * NF; i += 256) {
        // i = t*8 + f
        Wsh[i] = W2[(i >> 3) * CH3 + g * NF + (i & 7)];
    }
    if (tid < KW * NF) w3sh[tid] = k3[(tid >> 3) * CH3 + g * NF + (tid & 7)];
    if (tid < NF)      b3sh[tid] = b3[g * NF + tid];
    __syncthreads();

    // Hoist conv weights + bias to registers (constant-indexed after full unroll)
    float w3r[KW * NF];
    #pragma unroll
    for (int i = 0; i < KW * NF; i++) w3r[i] = w3sh[i];
    float b3r[NF];
    #pragma unroll
    for (int f = 0; f < NF; f++) b3r[f] = b3sh[f];

    const int b  = tid >> 2;                // 0..63
    const int tq = tid & 3;                 // 0..3  -> t range [tq*29, tq*29+28]
    const float* __restrict__ xrow = &xall[b * L2];

    float acc0 = 0.f, acc1 = 0.f;
    const int t0 = tq * 29;
    float x0 = xrow[t0],     x1v = xrow[t0 + 1], x2v = xrow[t0 + 2];
    float x3v = xrow[t0 + 3], x4v = xrow[t0 + 4];

    for (int s = 0; s < 29; s++) {
        const int t = t0 + s;
        #pragma unroll
        for (int f = 0; f < NF; f++) {
            float y = b3r[f];
            y = fmaf(x0,  w3r[f],      y);
            y = fmaf(x1v, w3r[8 + f],  y);
            y = fmaf(x2v, w3r[16 + f], y);
            y = fmaf(x3v, w3r[24 + f], y);
            y = fmaf(x4v, w3r[32 + f], y);
            y = fmaxf(y, 0.f);
            float2 w = Wsh[t * NF + f];
            acc0 = fmaf(y, w.x, acc0);
            acc1 = fmaf(y, w.y, acc1);
        }
        // slide window
        x0 = x1v; x1v = x2v; x2v = x3v; x3v = x4v;
        x4v = (s < 28) ? xrow[t + 5] : 0.f;
    }

    // Reduce the 4 threads (adjacent lanes) that share a batch
    acc0 += __shfl_down_sync(0xffffffffu, acc0, 2);
    acc0 += __shfl_down_sync(0xffffffffu, acc0, 1);
    acc1 += __shfl_down_sync(0xffffffffu, acc1, 2);
    acc1 += __shfl_down_sync(0xffffffffu, acc1, 1);
    if (tq == 0) {
        atomicAdd(&g_partial[(b * 2 + 0) * 32], acc0);
        atomicAdd(&g_partial[(b * 2 + 1) * 32], acc1);
    }
}

// ---------------------------------------------------------------------------
// Finalize: bias + tanh
// ---------------------------------------------------------------------------
__global__ void k_final(const float* __restrict__ bd, float* __restrict__ out) {
    const int i = threadIdx.x;                 // 0..127 = b*2 + a
    out[i] = tanhf(g_partial[i * 32] + bd[i & 1]);
}

// ---------------------------------------------------------------------------
extern "C" void kernel_launch(void* const* d_in, const int* in_sizes, int n_in,
                              void* d_out, int out_size) {
    const float* state = (const float*)d_in[0];
    const float* k1    = (const float*)d_in[1];
    const float* b1    = (const float*)d_in[2];
    const float* k2    = (const float*)d_in[3];
    const float* b2    = (const float*)d_in[4];
    const float* k3    = (const float*)d_in[5];
    const float* b3    = (const float*)d_in[6];
    const float* W     = (const float*)d_in[7];
    const float* bd    = (const float*)d_in[8];
    float* out = (float*)d_out;

    k_block1<<<dim3(16, 64), 128>>>(state, k1, b1);
    k_block2<<<dim3(128, 64), 128>>>(k2, b2);
    k_block3_dense<<<1024, 256>>>(k3, b3, W);
    k_final<<<1, 128>>>(bd, out);
}

// round 8
// speedup vs baseline: 1.8555x; 1.8555x over previous
#include <cuda_runtime.h>

// Shapes (fixed):
//   state: [64, 128, 16]
//   block1: cols=16   -> x1 [64, 128ch, 124]   (kernel 1, materialized)
//   block2: cols=128  -> x2 [64, 1024ch, 120]  (FUSED: channel g used only by group g)
//   block3: cols=1024 -> x3 [64, 8192ch, 116]  (FUSED with dense, never stored)
//   dense:  feat = t*8192 + ch3, W [950272,2], out = tanh(x@W + bd) -> [64, 2]

#define Bz   64
#define Lin  128
#define Cin  16
#define KW   5
#define NF   8
#define L1   124
#define CH1  128
#define L2   120
#define CH2  1024
#define L3   116
#define CH3  8192

// __device__ scratch (allocation-free rule)
__device__ float g_x1[Bz * CH1 * L1];     // 4.06 MB
__device__ float g_partial[128 * 32];     // [b*2+a] stride 32 floats (128B) -> distinct L2 lines
__device__ unsigned int g_done;

// ---------------------------------------------------------------------------
// packed f32x2 helpers (Blackwell FFMA2 — 2x fp32 per FMA-pipe issue)
// ---------------------------------------------------------------------------
typedef unsigned long long u64p;

__device__ __forceinline__ u64p f2pk(float lo, float hi) {
    u64p r; asm("mov.b64 %0, {%1,%2};" : "=l"(r) : "f"(lo), "f"(hi)); return r;
}
__device__ __forceinline__ void f2un(float& lo, float& hi, u64p v) {
    asm("mov.b64 {%0,%1}, %2;" : "=f"(lo), "=f"(hi) : "l"(v));
}
__device__ __forceinline__ u64p f2fma(u64p a, u64p b, u64p c) {
    u64p d; asm("fma.rn.f32x2 %0, %1, %2, %3;" : "=l"(d) : "l"(a), "l"(b), "l"(c)); return d;
}
__device__ __forceinline__ u64p f2relu(u64p v) {
    float lo, hi; f2un(lo, hi, v);
    return f2pk(fmaxf(lo, 0.f), fmaxf(hi, 0.f));   // FMNMX = alu pipe, off the fma pipe
}

// ---------------------------------------------------------------------------
// Block 1: one CTA per (c, b). Also resets the reduction scratch.
// ---------------------------------------------------------------------------
__global__ void k_block1(const float* __restrict__ state,
                         const float* __restrict__ k1,
                         const float* __restrict__ b1) {
    const int c = blockIdx.x, b = blockIdx.y, tid = threadIdx.x;

    if (blockIdx.x == 0 && blockIdx.y == 0) {
        for (int j = tid; j < 128 * 32; j += 128) g_partial[j] = 0.f;
        if (tid == 0) g_done = 0u;
    }

    __shared__ float ssh[Lin];
    __shared__ float wsh[KW * NF];
    __shared__ float bsh[NF];

    ssh[tid] = state[(b * Lin + tid) * Cin + c];             // x[b,c,l] = state[b,l,c]
    if (tid < KW * NF) wsh[tid] = k1[(tid >> 3) * CH1 + c * NF + (tid & 7)];
    if (tid < NF)      bsh[tid] = b1[c * NF + tid];
    __syncthreads();

    for (int i = tid; i < NF * L1; i += 128) {
        int f = i / L1, t = i - f * L1;
        float y = bsh[f];
        #pragma unroll
        for (int k = 0; k < KW; k++) y = fmaf(ssh[t + k], wsh[k * NF + f], y);
        g_x1[(b * CH1 + c * NF + f) * L1 + t] = fmaxf(y, 0.f);
    }
}

// ---------------------------------------------------------------------------
// Fused block2 + block3 + dense + (last-CTA) tanh epilogue.
// One CTA per channel-group g in [0,1024). 256 threads.
//   Phase A: stage x1[b, g>>3, :] in 16-batch chunks, compute x2[b,g,:] -> smem
//   Phase B: conv3 (f32x2-packed over filter pairs) + dense dot, sliding window
//   Reduce:  warp-shfl over the 4 t-quarters, 128-byte-strided atomics
//   Epilogue: ticket-elected last CTA applies bias + tanh, writes d_out
// ---------------------------------------------------------------------------
__global__ void __launch_bounds__(256) k_fused(
        const float* __restrict__ k2, const float* __restrict__ b2,
        const float* __restrict__ k3, const float* __restrict__ b3,
        const float* __restrict__ W,
        const float* __restrict__ bd, float* __restrict__ out) {
    const int g = blockIdx.x, tid = threadIdx.x;
    const int c = g >> 3;                     // parent x1 channel

    __shared__ float      x2sh[Bz * L2];      // 30720 B
    __shared__ ulonglong2 Wcomb[L3 * 4];      // 7424 B: per (t,p): {a0 f-pair, a1 f-pair}
    __shared__ float      x1ch[16 * L1];      // 7936 B: 16-batch staging of x1 channel c
    __shared__ unsigned   lastf;

    // ---- W -> packed smem (f-pairs per action), read exactly once from DRAM ----
    // float index of W[feat, a] = feat*2 + a; feat0 = t*8192 + g*8 + 2p (even).
    // float4 index = (feat0*2)/4 = t*4096 + g*4 + p.   [round-4 bug: was t*8192]
    const float4* __restrict__ W4 = (const float4*)W;
    for (int i = tid; i < L3 * 4; i += 256) {
        int t = i >> 2, p = i & 3;
        float4 v = W4[t * 4096 + g * 4 + p];
        // v = { W[f0,a0], W[f0,a1], W[f0+1,a0], W[f0+1,a1] }
        Wcomb[i] = make_ulonglong2(f2pk(v.x, v.z), f2pk(v.y, v.w));
    }

    // ---- block2 weights for this channel (broadcast loads) ----
    float w2r[KW];
    #pragma unroll
    for (int k = 0; k < KW; k++) w2r[k] = k2[k * CH2 + g];
    const float b2g = b2[g];

    // ---- Phase A: x2[b,g,:] for all 64 batches, via 16-batch smem chunks ----
    for (int cc = 0; cc < 4; cc++) {
        for (int i = tid; i < 16 * L1; i += 256) {
            int bl = i / L1, t = i - bl * L1;
            x1ch[i] = g_x1[((cc * 16 + bl) * CH1 + c) * L1 + t];
        }
        __syncthreads();
        for (int i = tid; i < 16 * L2; i += 256) {
            int bl = i / L2, t = i - bl * L2;
            float y = b2g;
            #pragma unroll
            for (int k = 0; k < KW; k++) y = fmaf(x1ch[bl * L1 + t + k], w2r[k], y);
            x2sh[(cc * 16 + bl) * L2 + t] = fmaxf(y, 0.f);
        }
        __syncthreads();
    }

    // ---- block3 weights, packed over filter pairs ----
    const float2* __restrict__ k3v = (const float2*)k3;   // (k*8192+g*8) even -> 8B aligned
    u64p w3p[KW][4], b3p[4];
    #pragma unroll
    for (int k = 0; k < KW; k++)
        #pragma unroll
        for (int p = 0; p < 4; p++) {
            float2 v = k3v[k * (CH3 >> 1) + g * 4 + p];
            w3p[k][p] = f2pk(v.x, v.y);
        }
    {
        const float2* __restrict__ b3v = (const float2*)b3;
        #pragma unroll
        for (int p = 0; p < 4; p++) {
            float2 v = b3v[g * 4 + p];
            b3p[p] = f2pk(v.x, v.y);
        }
    }

    // ---- Phase B: main loop. thread = (batch, t-quarter) ----
    const int b  = tid >> 2;
    const int tq = tid & 3;
    const int t0 = tq * 29;
    const float* __restrict__ xrow = &x2sh[b * L2];

    u64p x0 = f2pk(xrow[t0],     xrow[t0]);
    u64p x1 = f2pk(xrow[t0 + 1], xrow[t0 + 1]);
    u64p x2 = f2pk(xrow[t0 + 2], xrow[t0 + 2]);
    u64p x3 = f2pk(xrow[t0 + 3], xrow[t0 + 3]);
    u64p x4 = f2pk(xrow[t0 + 4], xrow[t0 + 4]);

    u64p acc0 = 0ull, acc1 = 0ull;            // packed zeros

    for (int s = 0; s < 29; s++) {
        u64p y0 = b3p[0], y1 = b3p[1], y2 = b3p[2], y3 = b3p[3];
        // conv3: 20 packed FMAs (vs 40 scalar)
        y0 = f2fma(x0, w3p[0][0], y0); y1 = f2fma(x0, w3p[0][1], y1);
        y2 = f2fma(x0, w3p[0][2], y2); y3 = f2fma(x0, w3p[0][3], y3);
        y0 = f2fma(x1, w3p[1][0], y0); y1 = f2fma(x1, w3p[1][1], y1);
        y2 = f2fma(x1, w3p[1][2], y2); y3 = f2fma(x1, w3p[1][3], y3);
        y0 = f2fma(x2, w3p[2][0], y0); y1 = f2fma(x2, w3p[2][1], y1);
        y2 = f2fma(x2, w3p[2][2], y2); y3 = f2fma(x2, w3p[2][3], y3);
        y0 = f2fma(x3, w3p[3][0], y0); y1 = f2fma(x3, w3p[3][1], y1);
        y2 = f2fma(x3, w3p[3][2], y2); y3 = f2fma(x3, w3p[3][3], y3);
        y0 = f2fma(x4, w3p[4][0], y0); y1 = f2fma(x4, w3p[4][1], y1);
        y2 = f2fma(x4, w3p[4][2], y2); y3 = f2fma(x4, w3p[4][3], y3);
        // relu (alu pipe)
        y0 = f2relu(y0); y1 = f2relu(y1); y2 = f2relu(y2); y3 = f2relu(y3);
        // dense: 8 packed FMAs (vs 16 scalar), LDS.128 per p
        const ulonglong2* __restrict__ wr = &Wcomb[(t0 + s) * 4];
        acc0 = f2fma(y0, wr[0].x, acc0); acc1 = f2fma(y0, wr[0].y, acc1);
        acc0 = f2fma(y1, wr[1].x, acc0); acc1 = f2fma(y1, wr[1].y, acc1);
        acc0 = f2fma(y2, wr[2].x, acc0); acc1 = f2fma(y2, wr[2].y, acc1);
        acc0 = f2fma(y3, wr[3].x, acc0); acc1 = f2fma(y3, wr[3].y, acc1);
        // slide window
        x0 = x1; x1 = x2; x2 = x3; x3 = x4;
        float nv = (s < 28) ? xrow[t0 + s + 5] : 0.f;
        x4 = f2pk(nv, nv);
    }

    float lo, hi, s0, s1;
    f2un(lo, hi, acc0); s0 = lo + hi;
    f2un(lo, hi, acc1); s1 = lo + hi;

    // reduce the 4 consecutive lanes sharing a batch
    s0 += __shfl_down_sync(0xffffffffu, s0, 2);
    s0 += __shfl_down_sync(0xffffffffu, s0, 1);
    s1 += __shfl_down_sync(0xffffffffu, s1, 2);
    s1 += __shfl_down_sync(0xffffffffu, s1, 1);
    if (tq == 0) {
        atomicAdd(&g_partial[(b * 2 + 0) * 32], s0);
        atomicAdd(&g_partial[(b * 2 + 1) * 32], s1);
    }

    // ---- last-CTA epilogue: bias + tanh ----
    __syncthreads();
    if (tid == 0) {
        __threadfence();
        lastf = (atomicAdd(&g_done, 1u) == (unsigned)(gridDim.x - 1));
    }
    __syncthreads();
    if (lastf && tid < 128) {
        __threadfence();
        float v = *((volatile float*)&g_partial[tid * 32]);
        out[tid] = tanhf(v + bd[tid & 1]);
    }
}

// ---------------------------------------------------------------------------
extern "C" void kernel_launch(void* const* d_in, const int* in_sizes, int n_in,
                              void* d_out, int out_size) {
    const float* state = (const float*)d_in[0];
    const float* k1    = (const float*)d_in[1];
    const float* b1    = (const float*)d_in[2];
    const float* k2    = (const float*)d_in[3];
    const float* b2    = (const float*)d_in[4];
    const float* k3    = (const float*)d_in[5];
    const float* b3    = (const float*)d_in[6];
    const float* W     = (const float*)d_in[7];
    const float* bd    = (const float*)d_in[8];
    float* out = (float*)d_out;

    k_block1<<<dim3(16, 64), 128>>>(state, k1, b1);
    k_fused<<<1024, 256>>>(k2, b2, k3, b3, W, bd, out);
}